// round 16
// baseline (speedup 1.0000x reference)
#include <cuda_runtime.h>
#include <math.h>

#define CC   256
#define HH   40
#define WW   40
#define NROI 64
#define PHB  7
#define PWB  7
#define HW   1600
#define NBLK 512
#define TILE_MAX (7 * 32 * 40)   // nr<=7 rows x 32 ch x wbp<=40

// persistent scratch (no device allocs allowed)
__device__ float g_s[HW];
__device__ int   g_smax_bits;   // float bits; s>0 -> int-max == float-max; idempotent
__device__ int   g_cnt;         // monotonic barrier counter (never reset)

// ---------------------------------------------------------------------------
// Persistent fused kernel with per-bin SMEM staging.
// 512 blocks x 256 threads; 42.5KB static smem -> 5 blocks/SM, all 512
// resident -> stateless spin barrier safe. bid -> (ROI=bid&63, cg=bid>>6
// of 32 channels).
// For each of the 7 ph-bins: bulk-copy the bin rows x padded-x-span x 32ch
// from fm into smem (float4 streaming, mask premultiplied) -> reduce bins
// from smem (29cy LDS, unrolled) -> repeat. Converts the L2-latency-bound
// inner loop (measured ~10% warp duty across R9..R15) into streaming copy
// + issue-bound smem reduce.
// ---------------------------------------------------------------------------
__global__ void __launch_bounds__(256, 5)
k_fused(const float* __restrict__ fm,
        const float* __restrict__ rois1,
        const float* __restrict__ rois2,
        float* __restrict__ out) {
    __shared__ __align__(16) float smask[HW];
    __shared__ __align__(16) float stile[TILE_MAX];
    __shared__ float sred[64];
    const int bid = blockIdx.x;
    const int t   = threadIdx.x;
    const int w   = t >> 5, l = t & 31;

    // ---- Phase A: channel sums for pixels [bid*8, bid*8+8) (blocks 0..199)
    if (bid < 200) {
        const int px = t & 7;
        const int cs = t >> 3;              // 0..31, 8 channels each
        const float* f = fm + cs * 8 * HW + bid * 8 + px;
        float s = f[0] + f[HW] + f[2 * HW] + f[3 * HW]
                + f[4 * HW] + f[5 * HW] + f[6 * HW] + f[7 * HW];
        s += __shfl_down_sync(0xffffffffu, s, 16);
        s += __shfl_down_sync(0xffffffffu, s, 8);
        if (l < 8) sred[w * 8 + l] = s;     // [warp][px]
        __syncthreads();
        if (t < 8) {
            float acc = 0.f;
#pragma unroll
            for (int ww = 0; ww < 8; ww++) acc += sred[ww * 8 + t];
            g_s[bid * 8 + t] = acc;
#pragma unroll
            for (int o = 4; o; o >>= 1)
                acc = fmaxf(acc, __shfl_down_sync(0xffu, acc, o));
            if (t == 0) atomicMax(&g_smax_bits, __float_as_int(acc));
            __threadfence();
        }
    }
    __syncthreads();

    // ---- stateless grid barrier (monotonic counter, never reset) ----
    if (t == 0) {
        int ticket = atomicAdd(&g_cnt, 1);
        int target = (ticket / NBLK + 1) * NBLK;
        while (*(volatile int*)&g_cnt < target) { }
    }
    __syncthreads();

    const float smax = __int_as_float(*(volatile int*)&g_smax_bits);
    const float inv  = 1.0f / smax;

    // ---- ROI decode: round-half-even (jnp.round); clamp upper side only ----
    const int n   = bid & 63;
    const int cgi = bid >> 6;               // 0..7: channels [cgi*32, +32)
    const float* a = rois1 + n * 5;
    const float* b = rois2 + n * 5;
    int x1a = min(__float2int_rn(a[1] * 0.0625f), WW - 1);
    int y1a = min(__float2int_rn(a[2] * 0.0625f), HH - 1);
    int x2a = min(__float2int_rn(a[3] * 0.0625f), WW - 1);
    int y2a = min(__float2int_rn(a[4] * 0.0625f), HH - 1);
    int x1b = min(__float2int_rn(b[1] * 0.0625f), WW - 1);
    int y1b = min(__float2int_rn(b[2] * 0.0625f), HH - 1);
    int x2b = min(__float2int_rn(b[3] * 0.0625f), WW - 1);
    int y2b = min(__float2int_rn(b[4] * 0.0625f), HH - 1);
    const int ux1 = min(x1a, x1b), uy1 = min(y1a, y1b);
    const int ux2 = max(x2a, x2b), uy2 = max(y2a, y2b);
    const int hb = uy2 - uy1 + 1;
    const int wb = ux2 - ux1 + 1;

    // ---- effective mask, row per warp (rows uy1..uy2, full width) ----
    for (int ry = w; ry < hb; ry += 8) {
        const int y = uy1 + ry;
        const int idx = y * WW + l;
        {
            const int x = l;
            bool inA = (x >= x1a) & (x <= x2a) & (y >= y1a) & (y <= y2a);
            bool inB = (x >= x1b) & (x <= x2b) & (y >= y1b) & (y <= y2b);
            float s  = __ldcg(&g_s[idx]);
            float xx = s * inv;
            float x2 = xx * xx;
            smask[idx] = (inA || inB) ? 1.0f : (0.5f + 0.4f * (x2 * x2));
        }
        if (l < 8) {
            const int x = l + 32;
            bool inA = (x >= x1a) & (x <= x2a) & (y >= y1a) & (y <= y2a);
            bool inB = (x >= x1b) & (x <= x2b) & (y >= y1b) & (y <= y2b);
            float s  = __ldcg(&g_s[idx + 32]);
            float xx = s * inv;
            float x2 = xx * xx;
            smask[idx + 32] = (inA || inB) ? 1.0f : (0.5f + 0.4f * (x2 * x2));
        }
    }
    __syncthreads();

    // ---- per-bin staged pooling ----
    const int c0  = cgi * 32;
    const int x0  = ux1 & ~3;               // float4-aligned x start
    const int xq  = x0 >> 2;
    const int wbp = (ux2 | 3) - x0 + 1;     // padded span, multiple of 4, <=40
    const int w4  = wbp >> 2;
    const float4* fm4    = (const float4*)fm;
    const float4* smask4 = (const float4*)smask;
    float4* stile4 = (float4*)stile;

    // reduce mapping: thread t -> (ch = t>>3, pw = t&7), active pw < 7
    const int rch = t >> 3;
    const int rpw = t & 7;
    int xs = 0, xe = 0;
    if (rpw < 7) {
        xs = ux1 + (rpw * wb) / 7 - x0;
        xe = ux1 + ((rpw + 1) * wb + 6) / 7 - x0;
    }

    for (int ph = 0; ph < PHB; ph++) {
        const int ys = uy1 + (ph * hb) / 7;
        const int ye = uy1 + ((ph + 1) * hb + 6) / 7;
        const int nr = ye - ys;             // <= 7

        // ---- stage: rows [ys,ye) x [x0, x0+wbp) x 32ch, mask premultiplied
        const int nr32 = nr * 32;
        for (int rc = t >> 2; rc < nr32; rc += 64) {
            const int r  = rc >> 5;
            const int ch = rc & 31;
            const int y  = ys + r;
            const float4* src = fm4 + (c0 + ch) * 400 + y * 10 + xq;
            const float4* msk = smask4 + y * 10 + xq;
            float4* dst = stile4 + rc * w4;
            for (int x4 = t & 3; x4 < w4; x4 += 4) {
                float4 v = src[x4];
                float4 m = msk[x4];
                v.x *= m.x; v.y *= m.y; v.z *= m.z; v.w *= m.w;
                dst[x4] = v;
            }
        }
        __syncthreads();

        // ---- reduce from smem: thread (ch, pw) ----
        if (rpw < 7) {
            float acc = -INFINITY;
            for (int r = 0; r < nr; r++) {
                const float* row = stile + (r * 32 + rch) * wbp;
#pragma unroll
                for (int dx = 0; dx < 7; dx++)
                    if (xs + dx < xe) acc = fmaxf(acc, row[xs + dx]);
            }
            out[((n * CC + c0 + rch) * PHB + ph) * PWB + rpw] = acc;
        }
        __syncthreads();                    // protect stile before next stage
    }
}

// ---------------------------------------------------------------------------
extern "C" void kernel_launch(void* const* d_in, const int* in_sizes, int n_in,
                              void* d_out, int out_size) {
    const float* fm = (const float*)d_in[0];
    const float* r1 = (const float*)d_in[1];
    const float* r2 = (const float*)d_in[2];
    float* out = (float*)d_out;

    k_fused<<<NBLK, 256>>>(fm, r1, r2, out);
}

// round 17
// speedup vs baseline: 1.9449x; 1.9449x over previous
#include <cuda_runtime.h>
#include <math.h>

#define CC   256
#define HH   40
#define WW   40
#define NROI 64
#define PHB  7
#define PWB  7
#define HW   1600
#define NBLK 256

// dynamic smem: smask[1600] then rbuf[16 warps][7 ph][4 ch][40]
#define RB_PH  (4 * 40)
#define RB_W   (7 * RB_PH)
#define SMEM_DYN ((HW + 16 * RB_W) * 4)

// persistent scratch (no device allocs allowed)
__device__ float g_s[HW];
__device__ int   g_smax_bits;   // float bits; s>0 -> int-max == float-max; idempotent
__device__ int   g_cnt;         // monotonic barrier counter (never reset)

// ---------------------------------------------------------------------------
// R7 consolidation. 256 blocks (64 ROIs x 4 channel quarters) x 512 threads,
// 78KB dynamic smem -> 2 blocks/SM, all resident -> spin barrier safe.
// Diffs vs R7 (best, 18.5us): phase A spread over 200 blocks (8px each,
// 2x parallelism); ROI decode hoisted before the barrier (overlaps spin).
// Pool: per warp, ALL 7 ph bins' row-maxes back-to-back with no syncs,
// then one syncwarp and all 7x4 bin reduces.
// ---------------------------------------------------------------------------
__global__ void __launch_bounds__(512, 2)
k_fused(const float* __restrict__ fm,
        const float* __restrict__ rois1,
        const float* __restrict__ rois2,
        float* __restrict__ out) {
    extern __shared__ float sm[];
    float* smask = sm;                          // [1600]
    __shared__ float sred[128];
    const int bid = blockIdx.x;
    const int t   = threadIdx.x;
    const int w   = t >> 5, l = t & 31;
    float* rb = sm + HW + w * RB_W;             // this warp's [7][4][40]

    // ---- ROI decode (input-only; overlaps the barrier spin) ----
    // round-half-even (matches jnp.round); clamp upper side only
    const int n   = bid >> 2;
    const int cgi = bid & 3;
    const float* a = rois1 + n * 5;
    const float* b = rois2 + n * 5;
    int x1a = min(__float2int_rn(a[1] * 0.0625f), WW - 1);
    int y1a = min(__float2int_rn(a[2] * 0.0625f), HH - 1);
    int x2a = min(__float2int_rn(a[3] * 0.0625f), WW - 1);
    int y2a = min(__float2int_rn(a[4] * 0.0625f), HH - 1);
    int x1b = min(__float2int_rn(b[1] * 0.0625f), WW - 1);
    int y1b = min(__float2int_rn(b[2] * 0.0625f), HH - 1);
    int x2b = min(__float2int_rn(b[3] * 0.0625f), WW - 1);
    int y2b = min(__float2int_rn(b[4] * 0.0625f), HH - 1);
    const int ux1 = min(x1a, x1b), uy1 = min(y1a, y1b);
    const int ux2 = max(x2a, x2b), uy2 = max(y2a, y2b);
    const int hb = uy2 - uy1 + 1;
    const int wb = ux2 - ux1 + 1;

    // ---- Phase A: channel sums for pixels [bid*8, bid*8+8) (blocks 0..199)
    if (bid < 200) {
        const int px = t & 7;                   // pixel within group
        const int cs = t >> 3;                  // 0..63, 4 channels each
        const float* f = fm + cs * 4 * HW + bid * 8 + px;
        float s = f[0] + f[HW] + f[2 * HW] + f[3 * HW];
        // lanes l, l+8, l+16, l+24 share px
        s += __shfl_down_sync(0xffffffffu, s, 16);
        s += __shfl_down_sync(0xffffffffu, s, 8);
        if (l < 8) sred[w * 8 + l] = s;         // [warp][px], 16 warps
        __syncthreads();
        if (t < 8) {
            float acc = 0.f;
#pragma unroll
            for (int ww = 0; ww < 16; ww++) acc += sred[ww * 8 + t];
            g_s[bid * 8 + t] = acc;
#pragma unroll
            for (int o = 4; o; o >>= 1)
                acc = fmaxf(acc, __shfl_down_sync(0xffu, acc, o));
            if (t == 0) atomicMax(&g_smax_bits, __float_as_int(acc));
            __threadfence();                    // release g_s / smax
        }
    }
    __syncthreads();

    // ---- stateless grid barrier (monotonic counter, never reset) ----
    if (t == 0) {
        int ticket = atomicAdd(&g_cnt, 1);
        int target = (ticket / NBLK + 1) * NBLK;
        while (*(volatile int*)&g_cnt < target) { }
    }
    __syncthreads();

    const float smax = __int_as_float(*(volatile int*)&g_smax_bits);
    const float inv  = 1.0f / smax;

    // ---- effective mask (rows uy1..uy2 only), g() computed inline ----
    for (int p = t; p < hb * WW; p += 512) {
        int y = uy1 + p / WW;
        int x = p % WW;
        int idx = y * WW + x;
        bool inA = (x >= x1a) & (x <= x2a) & (y >= y1a) & (y <= y2a);
        bool inB = (x >= x1b) & (x <= x2b) & (y >= y1b) & (y <= y2b);
        float s  = __ldcg(&g_s[idx]);
        float xx = s * inv;
        float x2 = xx * xx;
        smask[idx] = (inA || inB) ? 1.0f : (0.5f + 0.4f * (x2 * x2));
    }
    __syncthreads();

    // ---- phase 1: all 7 ph bins, no syncs ----
    const int c0 = cgi * 64 + w * 4;
    const int xg = ux1 + l;
    const bool wide = (wb > 32);
    const float* cbase = fm + c0 * HW;

#pragma unroll
    for (int ph = 0; ph < PHB; ph++) {
        int ys = uy1 + (ph * hb) / 7;
        int ye = uy1 + ((ph + 1) * hb + 6) / 7;
        const float* p0 = cbase + ys * WW + xg;
        const float* mp = smask + ys * WW + xg;
        float a0 = -INFINITY, a1 = -INFINITY, a2 = -INFINITY, a3 = -INFINITY;
        float* rphp = rb + ph * RB_PH;

        if (!wide) {
            if (l < wb) {
                int y = ys;
                for (; y + 1 < ye; y += 2) {
                    float m0 = mp[0], m1 = mp[WW];
                    float u0 = p0[0],           u1 = p0[HW];
                    float u2 = p0[2 * HW],      u3 = p0[3 * HW];
                    float v0 = p0[WW],          v1 = p0[HW + WW];
                    float v2 = p0[2 * HW + WW], v3 = p0[3 * HW + WW];
                    a0 = fmaxf(fmaxf(a0, u0 * m0), v0 * m1);
                    a1 = fmaxf(fmaxf(a1, u1 * m0), v1 * m1);
                    a2 = fmaxf(fmaxf(a2, u2 * m0), v2 * m1);
                    a3 = fmaxf(fmaxf(a3, u3 * m0), v3 * m1);
                    p0 += 2 * WW; mp += 2 * WW;
                }
                if (y < ye) {
                    float m0 = mp[0];
                    a0 = fmaxf(a0, p0[0]      * m0);
                    a1 = fmaxf(a1, p0[HW]     * m0);
                    a2 = fmaxf(a2, p0[2 * HW] * m0);
                    a3 = fmaxf(a3, p0[3 * HW] * m0);
                }
            }
            rphp[0 * 40 + l] = a0; rphp[1 * 40 + l] = a1;
            rphp[2 * 40 + l] = a2; rphp[3 * 40 + l] = a3;
        } else {
            float b0 = -INFINITY, b1 = -INFINITY, b2 = -INFINITY, b3 = -INFINITY;
            const bool act1 = (l + 32 < wb);
            for (int y = ys; y < ye; y++) {
                float m0 = mp[0];
                a0 = fmaxf(a0, p0[0]      * m0);
                a1 = fmaxf(a1, p0[HW]     * m0);
                a2 = fmaxf(a2, p0[2 * HW] * m0);
                a3 = fmaxf(a3, p0[3 * HW] * m0);
                if (act1) {
                    float m1 = mp[32];
                    b0 = fmaxf(b0, p0[32]          * m1);
                    b1 = fmaxf(b1, p0[HW + 32]     * m1);
                    b2 = fmaxf(b2, p0[2 * HW + 32] * m1);
                    b3 = fmaxf(b3, p0[3 * HW + 32] * m1);
                }
                p0 += WW; mp += WW;
            }
            rphp[0 * 40 + l] = a0; rphp[1 * 40 + l] = a1;
            rphp[2 * 40 + l] = a2; rphp[3 * 40 + l] = a3;
            if (l + 32 < 40) {
                rphp[0 * 40 + l + 32] = b0; rphp[1 * 40 + l + 32] = b1;
                rphp[2 * 40 + l + 32] = b2; rphp[3 * 40 + l + 32] = b3;
            }
        }
    }

    __syncwarp();

    // ---- phase 2: all bin reduces (lanes 0..27 -> (channel, pw-bin)) ----
    if (l < 28) {
        const int rci = l / 7;
        const int rpw = l - rci * 7;
        const int xs = (rpw * wb) / 7;
        const int xe = ((rpw + 1) * wb + 6) / 7;
        float* outn = out + (n * CC + c0 + rci) * (PHB * PWB) + rpw;
        const float* rc = rb + rci * 40;
#pragma unroll
        for (int ph = 0; ph < PHB; ph++) {
            const float* r = rc + ph * RB_PH;
            float mx = -INFINITY;
            for (int x = xs; x < xe; x++) mx = fmaxf(mx, r[x]);
            outn[ph * PWB] = mx;
        }
    }
}

// ---------------------------------------------------------------------------
extern "C" void kernel_launch(void* const* d_in, const int* in_sizes, int n_in,
                              void* d_out, int out_size) {
    const float* fm = (const float*)d_in[0];
    const float* r1 = (const float*)d_in[1];
    const float* r2 = (const float*)d_in[2];
    float* out = (float*)d_out;

    cudaFuncSetAttribute(k_fused, cudaFuncAttributeMaxDynamicSharedMemorySize, SMEM_DYN);
    k_fused<<<NBLK, 512, SMEM_DYN>>>(fm, r1, r2, out);
}